// round 5
// baseline (speedup 1.0000x reference)
#include <cuda_runtime.h>
#include <cstdint>

// Problem constants
constexpr int NN = 100000;   // nodes
constexpr int NE = 1600000;  // edges
constexpr int NF = 128;      // input feats
constexpr int NC = 40;       // classes (post-projection feature width)

// ---------------- scratch (static device globals; no allocation) -------------
__device__ __align__(256) float d_deg[NN];
__device__ __align__(256) float d_dis[NN];
__device__ __align__(256) int   d_cnt[NN];
__device__ __align__(256) int   d_off[NN];
__device__ __align__(256) int   d_cur[NN];
__device__ __align__(256) int2  d_edat[NE];   // (row, norm-as-bits), CSR by col
__device__ __align__(256) float d_hA[(size_t)NN * NC];
__device__ __align__(256) float d_hB[(size_t)NN * NC];

// ---------------- kernels ----------------------------------------------------

// zero deg (float) and cnt (int) in one pass
__global__ void zero2_kernel() {
    int i = blockIdx.x * blockDim.x + threadIdx.x;
    if (i < NN) { d_deg[i] = 0.0f; d_cnt[i] = 0; }
}

// deg[col] += ew and cnt[col] += 1 (guarded)
__global__ void degcnt_kernel(const int* __restrict__ row,
                              const int* __restrict__ col,
                              const float* __restrict__ ew) {
    int e = blockIdx.x * blockDim.x + threadIdx.x;
    if (e < NE) {
        int r = row[e];
        int c = col[e];
        if (c >= 0 && c < NN) {
            atomicAdd(&d_deg[c], ew[e]);
            if (r >= 0 && r < NN) atomicAdd(&d_cnt[c], 1);
        }
    }
}

__global__ void dis_kernel() {
    int i = blockIdx.x * blockDim.x + threadIdx.x;
    if (i < NN) {
        float d = d_deg[i];
        d_dis[i] = (d > 0.0f) ? rsqrtf(d) : 0.0f;
    }
}

// single-block exclusive scan of cnt -> off (also seeds cur)
__global__ void scan_kernel() {
    __shared__ int ssum[1024];
    const int T = 1024;
    const int C = (NN + T - 1) / T;   // 98 per thread
    int t = threadIdx.x;
    int base = t * C;
    int end = base + C; if (end > NN) end = NN;

    int s = 0;
    for (int i = base; i < end; i++) s += d_cnt[i];
    ssum[t] = s;
    __syncthreads();
    // Hillis-Steele inclusive scan over 1024 partials
    for (int off = 1; off < T; off <<= 1) {
        int v = (t >= off) ? ssum[t - off] : 0;
        __syncthreads();
        ssum[t] += v;
        __syncthreads();
    }
    int prefix = (t == 0) ? 0 : ssum[t - 1];
    for (int i = base; i < end; i++) {
        d_off[i] = prefix;
        d_cur[i] = prefix;
        prefix += d_cnt[i];
    }
}

// CSR fill: norm computed inline, scattered to slot via cursor bump.
// After this kernel: edges of node c live in edat[off[c] .. cur[c]).
__global__ void fill_kernel(const int* __restrict__ row,
                            const int* __restrict__ col,
                            const float* __restrict__ ew) {
    int e = blockIdx.x * blockDim.x + threadIdx.x;
    if (e < NE) {
        int r = row[e];
        int c = col[e];
        if (r >= 0 && r < NN && c >= 0 && c < NN) {
            float w = d_dis[r] * ew[e] * d_dis[c];
            int pos = atomicAdd(&d_cur[c], 1);
            d_edat[pos] = make_int2(r, __float_as_int(w));
        }
    }
}

// y[NN,40] = x[NN,128] @ W[128,40]
__global__ void xw_kernel(const float* __restrict__ x,
                          const float* __restrict__ W,
                          float* __restrict__ y) {
    __shared__ float sW[NF * NC];   // 20 KB
    __shared__ float sh[32][65];    // 8.3 KB (padded)
    int t = threadIdx.x;
    int nb = blockIdx.x * 64;

    for (int i = t; i < NF * NC; i += 128) sW[i] = W[i];

    int ng = t & 15;
    int cg = t >> 4;
    float acc[4][5] = {};

    for (int kc = 0; kc < NF; kc += 32) {
        __syncthreads();
        for (int i = t; i < 64 * 32; i += 128) {
            int n = i >> 5, k = i & 31;
            int node = nb + n;
            sh[k][n] = (node < NN) ? x[(size_t)node * NF + kc + k] : 0.0f;
        }
        __syncthreads();
        #pragma unroll 8
        for (int k = 0; k < 32; k++) {
            float hv[4], wv[5];
            #pragma unroll
            for (int i = 0; i < 4; i++) hv[i] = sh[k][ng * 4 + i];
            #pragma unroll
            for (int j = 0; j < 5; j++) wv[j] = sW[(kc + k) * NC + cg * 5 + j];
            #pragma unroll
            for (int i = 0; i < 4; i++)
                #pragma unroll
                for (int j = 0; j < 5; j++)
                    acc[i][j] += hv[i] * wv[j];
        }
    }
    #pragma unroll
    for (int i = 0; i < 4; i++) {
        int node = nb + ng * 4 + i;
        if (node < NN) {
            #pragma unroll
            for (int j = 0; j < 5; j++)
                y[(size_t)node * NC + cg * 5 + j] = acc[i][j];
        }
    }
}

// Pull-mode hop: half-warp (16 lanes, 10 active) per destination node.
// acc[40] in registers as float4; one streaming 160B store per node. No atomics.
__global__ void hop_pull(const float* __restrict__ hin,
                         float* __restrict__ hout) {
    int hw  = (blockIdx.x * blockDim.x + threadIdx.x) >> 4;  // node id
    if (hw >= NN) return;
    int sub = threadIdx.x & 15;
    if (sub >= 10) return;   // 40 floats = 10 float4 lanes

    int s = d_off[hw];
    int e = d_cur[hw];

    float4 acc = make_float4(0.f, 0.f, 0.f, 0.f);
    int i = s;
    // unroll by 2 for MLP on the gather
    for (; i + 2 <= e; i += 2) {
        int2 e0 = d_edat[i];
        int2 e1 = d_edat[i + 1];
        float w0 = __int_as_float(e0.y);
        float w1 = __int_as_float(e1.y);
        float4 v0 = __ldg(reinterpret_cast<const float4*>(hin + (size_t)e0.x * NC) + sub);
        float4 v1 = __ldg(reinterpret_cast<const float4*>(hin + (size_t)e1.x * NC) + sub);
        acc.x += v0.x * w0; acc.y += v0.y * w0; acc.z += v0.z * w0; acc.w += v0.w * w0;
        acc.x += v1.x * w1; acc.y += v1.y * w1; acc.z += v1.z * w1; acc.w += v1.w * w1;
    }
    if (i < e) {
        int2 e0 = d_edat[i];
        float w0 = __int_as_float(e0.y);
        float4 v0 = __ldg(reinterpret_cast<const float4*>(hin + (size_t)e0.x * NC) + sub);
        acc.x += v0.x * w0; acc.y += v0.y * w0; acc.z += v0.z * w0; acc.w += v0.w * w0;
    }
    *reinterpret_cast<float4*>(hout + (size_t)hw * NC + sub * 4) = acc;
}

// ---------------- launch ------------------------------------------------------

extern "C" void kernel_launch(void* const* d_in, const int* in_sizes, int n_in,
                              void* d_out, int out_size) {
    // Resolve inputs BY ELEMENT COUNT (order-independent; all counts distinct):
    //   x: 12,800,000   edge_index: 3,200,000 (int32)   edge_weight: 1,600,000   W: 5,120
    const float* x  = nullptr;
    const int*   ei = nullptr;
    const float* ew = nullptr;
    const float* W  = nullptr;
    for (int i = 0; i < n_in; i++) {
        long long sz = in_sizes[i];
        if      (sz == (long long)NN * NF) x  = (const float*)d_in[i];
        else if (sz == (long long)2 * NE)  ei = (const int*)d_in[i];
        else if (sz == (long long)NE)      ew = (const float*)d_in[i];
        else if (sz == (long long)NF * NC) W  = (const float*)d_in[i];
    }
    float* out = (float*)d_out;

    const int* row = ei;        // edge_index[0, :]
    const int* col = ei + NE;   // edge_index[1, :]

    float* hA;  cudaGetSymbolAddress((void**)&hA, d_hA);
    float* hB;  cudaGetSymbolAddress((void**)&hB, d_hB);

    // --- prep: degrees, norm, CSR by destination ---
    zero2_kernel<<<(NN + 255)/256, 256>>>();
    degcnt_kernel<<<(NE + 255)/256, 256>>>(row, col, ew);
    dis_kernel<<<(NN + 255)/256, 256>>>();
    scan_kernel<<<1, 1024>>>();
    fill_kernel<<<(NE + 255)/256, 256>>>(row, col, ew);

    // --- project first: hA = x @ W ---
    xw_kernel<<<(NN + 63)/64, 128>>>(x, W, hA);

    // --- three pull-mode hops (no zeroing needed, no atomics) ---
    const int HOP_BLOCKS = (NN * 16 + 255) / 256;   // 16 threads per node
    hop_pull<<<HOP_BLOCKS, 256>>>(hA, hB);
    hop_pull<<<HOP_BLOCKS, 256>>>(hB, hA);
    hop_pull<<<HOP_BLOCKS, 256>>>(hA, out);
}

// round 6
// speedup vs baseline: 1.7108x; 1.7108x over previous
#include <cuda_runtime.h>
#include <cstdint>

// Problem constants
constexpr int NN = 100000;   // nodes
constexpr int NE = 1600000;  // edges
constexpr int NF = 128;      // input feats
constexpr int NC = 40;       // classes (post-projection feature width)

// ---------------- scratch (static device globals; no allocation) -------------
__device__ __align__(256) float d_deg[NN];
__device__ __align__(256) float d_dis[NN];
__device__ __align__(256) int   d_cnt[NN];
__device__ __align__(256) int   d_off[NN];
__device__ __align__(256) int   d_cur[NN];
__device__ int d_base;
__device__ __align__(256) int2  d_edat[NE];   // (row, norm-as-bits), CSR by col
__device__ __align__(256) float d_hA[(size_t)NN * NC];
__device__ __align__(256) float d_hB[(size_t)NN * NC];

// ---------------- kernels ----------------------------------------------------

// zero deg (float) and cnt (int); reset global scan cursor
__global__ void zero2_kernel() {
    int i = blockIdx.x * blockDim.x + threadIdx.x;
    if (i < NN) { d_deg[i] = 0.0f; d_cnt[i] = 0; }
    if (i == 0) d_base = 0;
}

// deg[col] += ew and cnt[col] += 1 (guarded)
__global__ void degcnt_kernel(const int* __restrict__ row,
                              const int* __restrict__ col,
                              const float* __restrict__ ew) {
    int e = blockIdx.x * blockDim.x + threadIdx.x;
    if (e < NE) {
        int r = row[e];
        int c = col[e];
        if (c >= 0 && c < NN) {
            atomicAdd(&d_deg[c], ew[e]);
            if (r >= 0 && r < NN) atomicAdd(&d_cnt[c], 1);
        }
    }
}

__global__ void dis_kernel() {
    int i = blockIdx.x * blockDim.x + threadIdx.x;
    if (i < NN) {
        float d = d_deg[i];
        d_dis[i] = (d > 0.0f) ? rsqrtf(d) : 0.0f;
    }
}

// Decoupled block scan: per-block shfl scan of 256 counts, one atomicAdd for
// the block's base. Offsets are NOT node-ordered — irrelevant for pull mode,
// each node only needs its own contiguous [off, off+cnt) range.
__global__ void scanb_kernel() {
    __shared__ int swarp[8];
    __shared__ int sbase;
    int t = threadIdx.x;
    int i = blockIdx.x * 256 + t;
    int v = (i < NN) ? d_cnt[i] : 0;

    // warp inclusive scan
    int incl = v;
    #pragma unroll
    for (int o = 1; o < 32; o <<= 1) {
        int n = __shfl_up_sync(0xffffffffu, incl, o);
        if ((t & 31) >= o) incl += n;
    }
    if ((t & 31) == 31) swarp[t >> 5] = incl;
    __syncthreads();
    if (t < 8) {
        int w = swarp[t];
        #pragma unroll
        for (int o = 1; o < 8; o <<= 1) {
            int n = __shfl_up_sync(0xffu, w, o);
            if (t >= o) w += n;
        }
        swarp[t] = w;
    }
    __syncthreads();
    int blockIncl = incl + ((t >= 32) ? swarp[(t >> 5) - 1] : 0);
    if (t == 255) sbase = atomicAdd(&d_base, blockIncl);
    __syncthreads();
    if (i < NN) {
        int off = sbase + blockIncl - v;   // exclusive within block + base
        d_off[i] = off;
        d_cur[i] = off;
    }
}

// CSR fill: norm computed inline, scattered to slot via cursor bump.
__global__ void fill_kernel(const int* __restrict__ row,
                            const int* __restrict__ col,
                            const float* __restrict__ ew) {
    int e = blockIdx.x * blockDim.x + threadIdx.x;
    if (e < NE) {
        int r = row[e];
        int c = col[e];
        if (r >= 0 && r < NN && c >= 0 && c < NN) {
            float w = d_dis[r] * ew[e] * d_dis[c];
            int pos = atomicAdd(&d_cur[c], 1);
            d_edat[pos] = make_int2(r, __float_as_int(w));
        }
    }
}

// y[NN,40] = x[NN,128] @ W[128,40]
__global__ void xw_kernel(const float* __restrict__ x,
                          const float* __restrict__ W,
                          float* __restrict__ y) {
    __shared__ float sW[NF * NC];   // 20 KB
    __shared__ float sh[32][65];    // 8.3 KB (padded)
    int t = threadIdx.x;
    int nb = blockIdx.x * 64;

    for (int i = t; i < NF * NC; i += 128) sW[i] = W[i];

    int ng = t & 15;
    int cg = t >> 4;
    float acc[4][5] = {};

    for (int kc = 0; kc < NF; kc += 32) {
        __syncthreads();
        for (int i = t; i < 64 * 32; i += 128) {
            int n = i >> 5, k = i & 31;
            int node = nb + n;
            sh[k][n] = (node < NN) ? x[(size_t)node * NF + kc + k] : 0.0f;
        }
        __syncthreads();
        #pragma unroll 8
        for (int k = 0; k < 32; k++) {
            float hv[4], wv[5];
            #pragma unroll
            for (int i = 0; i < 4; i++) hv[i] = sh[k][ng * 4 + i];
            #pragma unroll
            for (int j = 0; j < 5; j++) wv[j] = sW[(kc + k) * NC + cg * 5 + j];
            #pragma unroll
            for (int i = 0; i < 4; i++)
                #pragma unroll
                for (int j = 0; j < 5; j++)
                    acc[i][j] += hv[i] * wv[j];
        }
    }
    #pragma unroll
    for (int i = 0; i < 4; i++) {
        int node = nb + ng * 4 + i;
        if (node < NN) {
            #pragma unroll
            for (int j = 0; j < 5; j++)
                y[(size_t)node * NC + cg * 5 + j] = acc[i][j];
        }
    }
}

// Pull-mode hop: half-warp (16 lanes, 10 active) per destination node.
// acc[40] in registers as float4; one streaming 160B store per node. No atomics.
__global__ void hop_pull(const float* __restrict__ hin,
                         float* __restrict__ hout) {
    int hw  = (blockIdx.x * blockDim.x + threadIdx.x) >> 4;  // node id
    if (hw >= NN) return;
    int sub = threadIdx.x & 15;
    if (sub >= 10) return;   // 40 floats = 10 float4 lanes

    int s = d_off[hw];
    int e = d_cur[hw];

    float4 acc = make_float4(0.f, 0.f, 0.f, 0.f);
    int i = s;
    for (; i + 2 <= e; i += 2) {
        int2 e0 = d_edat[i];
        int2 e1 = d_edat[i + 1];
        float w0 = __int_as_float(e0.y);
        float w1 = __int_as_float(e1.y);
        float4 v0 = __ldg(reinterpret_cast<const float4*>(hin + (size_t)e0.x * NC) + sub);
        float4 v1 = __ldg(reinterpret_cast<const float4*>(hin + (size_t)e1.x * NC) + sub);
        acc.x += v0.x * w0; acc.y += v0.y * w0; acc.z += v0.z * w0; acc.w += v0.w * w0;
        acc.x += v1.x * w1; acc.y += v1.y * w1; acc.z += v1.z * w1; acc.w += v1.w * w1;
    }
    if (i < e) {
        int2 e0 = d_edat[i];
        float w0 = __int_as_float(e0.y);
        float4 v0 = __ldg(reinterpret_cast<const float4*>(hin + (size_t)e0.x * NC) + sub);
        acc.x += v0.x * w0; acc.y += v0.y * w0; acc.z += v0.z * w0; acc.w += v0.w * w0;
    }
    *reinterpret_cast<float4*>(hout + (size_t)hw * NC + sub * 4) = acc;
}

// ---------------- launch ------------------------------------------------------

extern "C" void kernel_launch(void* const* d_in, const int* in_sizes, int n_in,
                              void* d_out, int out_size) {
    // Resolve inputs BY ELEMENT COUNT (order-independent; all counts distinct)
    const float* x  = nullptr;
    const int*   ei = nullptr;
    const float* ew = nullptr;
    const float* W  = nullptr;
    for (int i = 0; i < n_in; i++) {
        long long sz = in_sizes[i];
        if      (sz == (long long)NN * NF) x  = (const float*)d_in[i];
        else if (sz == (long long)2 * NE)  ei = (const int*)d_in[i];
        else if (sz == (long long)NE)      ew = (const float*)d_in[i];
        else if (sz == (long long)NF * NC) W  = (const float*)d_in[i];
    }
    float* out = (float*)d_out;

    const int* row = ei;        // edge_index[0, :]
    const int* col = ei + NE;   // edge_index[1, :]

    float* hA;  cudaGetSymbolAddress((void**)&hA, d_hA);
    float* hB;  cudaGetSymbolAddress((void**)&hB, d_hB);

    // --- prep: degrees, norm, CSR by destination ---
    zero2_kernel<<<(NN + 255)/256, 256>>>();
    degcnt_kernel<<<(NE + 255)/256, 256>>>(row, col, ew);
    dis_kernel<<<(NN + 255)/256, 256>>>();
    scanb_kernel<<<(NN + 255)/256, 256>>>();
    fill_kernel<<<(NE + 255)/256, 256>>>(row, col, ew);

    // --- project first: hA = x @ W ---
    xw_kernel<<<(NN + 63)/64, 128>>>(x, W, hA);

    // --- three pull-mode hops (no zeroing needed, no atomics) ---
    const int HOP_BLOCKS = (NN * 16 + 255) / 256;   // 16 threads per node
    hop_pull<<<HOP_BLOCKS, 256>>>(hA, hB);
    hop_pull<<<HOP_BLOCKS, 256>>>(hB, hA);
    hop_pull<<<HOP_BLOCKS, 256>>>(hA, out);
}

// round 7
// speedup vs baseline: 1.9357x; 1.1315x over previous
#include <cuda_runtime.h>
#include <cuda_fp16.h>
#include <cstdint>

// Problem constants
constexpr int NN = 100000;   // nodes
constexpr int NE = 1600000;  // edges
constexpr int NF = 128;      // input feats
constexpr int NC = 40;       // classes (post-projection feature width)

// ---------------- scratch (static device globals; no allocation) -------------
__device__ __align__(256) float  d_deg[NN];
__device__ __align__(256) float  d_dis[NN];
__device__ __align__(256) int    d_cnt[NN];
__device__ __align__(256) int    d_off[NN];
__device__ __align__(256) int    d_cur[NN];
__device__ int d_base;
__device__ __align__(256) int2   d_edat[NE];   // (row, norm-as-bits), CSR by col
__device__ __align__(256) __half d_hA[(size_t)NN * NC];   // fp16 intermediates
__device__ __align__(256) __half d_hB[(size_t)NN * NC];

// ---------------- kernels ----------------------------------------------------

// zero deg (float) and cnt (int); reset global scan cursor
__global__ void zero2_kernel() {
    int i = blockIdx.x * blockDim.x + threadIdx.x;
    if (i < NN) { d_deg[i] = 0.0f; d_cnt[i] = 0; }
    if (i == 0) d_base = 0;
}

// deg[col] += ew and cnt[col] += 1 (guarded)
__global__ void degcnt_kernel(const int* __restrict__ row,
                              const int* __restrict__ col,
                              const float* __restrict__ ew) {
    int e = blockIdx.x * blockDim.x + threadIdx.x;
    if (e < NE) {
        int r = row[e];
        int c = col[e];
        if (c >= 0 && c < NN) {
            atomicAdd(&d_deg[c], ew[e]);
            if (r >= 0 && r < NN) atomicAdd(&d_cnt[c], 1);
        }
    }
}

// dis = rsqrt(deg) fused with decoupled block scan of cnt -> off/cur.
// Offsets are NOT node-ordered (block bases come from one atomic) — fine for
// pull mode, each node only needs its own contiguous range.
__global__ void scan_dis_kernel() {
    __shared__ int swarp[8];
    __shared__ int sbase;
    int t = threadIdx.x;
    int i = blockIdx.x * 256 + t;
    int v = 0;
    if (i < NN) {
        v = d_cnt[i];
        float d = d_deg[i];
        d_dis[i] = (d > 0.0f) ? rsqrtf(d) : 0.0f;
    }

    int incl = v;
    #pragma unroll
    for (int o = 1; o < 32; o <<= 1) {
        int n = __shfl_up_sync(0xffffffffu, incl, o);
        if ((t & 31) >= o) incl += n;
    }
    if ((t & 31) == 31) swarp[t >> 5] = incl;
    __syncthreads();
    if (t < 8) {
        int w = swarp[t];
        #pragma unroll
        for (int o = 1; o < 8; o <<= 1) {
            int n = __shfl_up_sync(0xffu, w, o);
            if (t >= o) w += n;
        }
        swarp[t] = w;
    }
    __syncthreads();
    int blockIncl = incl + ((t >= 32) ? swarp[(t >> 5) - 1] : 0);
    if (t == 255) sbase = atomicAdd(&d_base, blockIncl);
    __syncthreads();
    if (i < NN) {
        int off = sbase + blockIncl - v;
        d_off[i] = off;
        d_cur[i] = off;
    }
}

// CSR fill: norm computed inline, scattered to slot via cursor bump.
__global__ void fill_kernel(const int* __restrict__ row,
                            const int* __restrict__ col,
                            const float* __restrict__ ew) {
    int e = blockIdx.x * blockDim.x + threadIdx.x;
    if (e < NE) {
        int r = row[e];
        int c = col[e];
        if (r >= 0 && r < NN && c >= 0 && c < NN) {
            float w = d_dis[r] * ew[e] * d_dis[c];
            int pos = atomicAdd(&d_cur[c], 1);
            d_edat[pos] = make_int2(r, __float_as_int(w));
        }
    }
}

// y[NN,40] = x[NN,128] @ W[128,40], output stored fp16
__global__ void xw_kernel(const float* __restrict__ x,
                          const float* __restrict__ W,
                          __half* __restrict__ y) {
    __shared__ float sW[NF * NC];   // 20 KB
    __shared__ float sh[32][65];    // 8.3 KB (padded)
    int t = threadIdx.x;
    int nb = blockIdx.x * 64;

    for (int i = t; i < NF * NC; i += 128) sW[i] = W[i];

    int ng = t & 15;
    int cg = t >> 4;
    float acc[4][5] = {};

    for (int kc = 0; kc < NF; kc += 32) {
        __syncthreads();
        for (int i = t; i < 64 * 32; i += 128) {
            int n = i >> 5, k = i & 31;
            int node = nb + n;
            sh[k][n] = (node < NN) ? x[(size_t)node * NF + kc + k] : 0.0f;
        }
        __syncthreads();
        #pragma unroll 8
        for (int k = 0; k < 32; k++) {
            float hv[4], wv[5];
            #pragma unroll
            for (int i = 0; i < 4; i++) hv[i] = sh[k][ng * 4 + i];
            #pragma unroll
            for (int j = 0; j < 5; j++) wv[j] = sW[(kc + k) * NC + cg * 5 + j];
            #pragma unroll
            for (int i = 0; i < 4; i++)
                #pragma unroll
                for (int j = 0; j < 5; j++)
                    acc[i][j] += hv[i] * wv[j];
        }
    }
    #pragma unroll
    for (int i = 0; i < 4; i++) {
        int node = nb + ng * 4 + i;
        if (node < NN) {
            #pragma unroll
            for (int j = 0; j < 5; j++)
                y[(size_t)node * NC + cg * 5 + j] = __float2half(acc[i][j]);
        }
    }
}

// Pull hop, fp16 in / fp16 out. 5-lane group per node (row = 40 halves = 5 uint4),
// 6 nodes per warp (30/32 lanes active). fp32 accumulation. No atomics.
__global__ void hop_h2h(const __half* __restrict__ hin,
                        __half* __restrict__ hout) {
    int gwarp = (blockIdx.x * blockDim.x + threadIdx.x) >> 5;
    int ln = threadIdx.x & 31;
    if (ln >= 30) return;
    int node = gwarp * 6 + ln / 5;
    if (node >= NN) return;
    int sub = ln % 5;

    int s = d_off[node];
    int e = d_cur[node];

    float acc[8] = {};
    int i = s;
    for (; i + 2 <= e; i += 2) {
        int2 e0 = d_edat[i];
        int2 e1 = d_edat[i + 1];
        float w0 = __int_as_float(e0.y);
        float w1 = __int_as_float(e1.y);
        uint4 v0 = __ldg(reinterpret_cast<const uint4*>(hin + (size_t)e0.x * NC) + sub);
        uint4 v1 = __ldg(reinterpret_cast<const uint4*>(hin + (size_t)e1.x * NC) + sub);
        const unsigned* p0 = &v0.x;
        const unsigned* p1 = &v1.x;
        #pragma unroll
        for (int q = 0; q < 4; q++) {
            float2 f0 = __half22float2(*reinterpret_cast<const __half2*>(&p0[q]));
            float2 f1 = __half22float2(*reinterpret_cast<const __half2*>(&p1[q]));
            acc[2*q]   += f0.x * w0 + f1.x * w1;
            acc[2*q+1] += f0.y * w0 + f1.y * w1;
        }
    }
    if (i < e) {
        int2 e0 = d_edat[i];
        float w0 = __int_as_float(e0.y);
        uint4 v0 = __ldg(reinterpret_cast<const uint4*>(hin + (size_t)e0.x * NC) + sub);
        const unsigned* p0 = &v0.x;
        #pragma unroll
        for (int q = 0; q < 4; q++) {
            float2 f0 = __half22float2(*reinterpret_cast<const __half2*>(&p0[q]));
            acc[2*q]   += f0.x * w0;
            acc[2*q+1] += f0.y * w0;
        }
    }
    uint4 o;
    unsigned* po = &o.x;
    #pragma unroll
    for (int q = 0; q < 4; q++) {
        __half2 h = __floats2half2_rn(acc[2*q], acc[2*q+1]);
        po[q] = *reinterpret_cast<unsigned*>(&h);
    }
    *(reinterpret_cast<uint4*>(hout + (size_t)node * NC) + sub) = o;
}

// Final pull hop, fp16 in / fp32 out (writes d_out directly).
__global__ void hop_h2f(const __half* __restrict__ hin,
                        float* __restrict__ hout) {
    int gwarp = (blockIdx.x * blockDim.x + threadIdx.x) >> 5;
    int ln = threadIdx.x & 31;
    if (ln >= 30) return;
    int node = gwarp * 6 + ln / 5;
    if (node >= NN) return;
    int sub = ln % 5;

    int s = d_off[node];
    int e = d_cur[node];

    float acc[8] = {};
    int i = s;
    for (; i + 2 <= e; i += 2) {
        int2 e0 = d_edat[i];
        int2 e1 = d_edat[i + 1];
        float w0 = __int_as_float(e0.y);
        float w1 = __int_as_float(e1.y);
        uint4 v0 = __ldg(reinterpret_cast<const uint4*>(hin + (size_t)e0.x * NC) + sub);
        uint4 v1 = __ldg(reinterpret_cast<const uint4*>(hin + (size_t)e1.x * NC) + sub);
        const unsigned* p0 = &v0.x;
        const unsigned* p1 = &v1.x;
        #pragma unroll
        for (int q = 0; q < 4; q++) {
            float2 f0 = __half22float2(*reinterpret_cast<const __half2*>(&p0[q]));
            float2 f1 = __half22float2(*reinterpret_cast<const __half2*>(&p1[q]));
            acc[2*q]   += f0.x * w0 + f1.x * w1;
            acc[2*q+1] += f0.y * w0 + f1.y * w1;
        }
    }
    if (i < e) {
        int2 e0 = d_edat[i];
        float w0 = __int_as_float(e0.y);
        uint4 v0 = __ldg(reinterpret_cast<const uint4*>(hin + (size_t)e0.x * NC) + sub);
        const unsigned* p0 = &v0.x;
        #pragma unroll
        for (int q = 0; q < 4; q++) {
            float2 f0 = __half22float2(*reinterpret_cast<const __half2*>(&p0[q]));
            acc[2*q]   += f0.x * w0;
            acc[2*q+1] += f0.y * w0;
        }
    }
    float4* dst = reinterpret_cast<float4*>(hout + (size_t)node * NC + sub * 8);
    dst[0] = make_float4(acc[0], acc[1], acc[2], acc[3]);
    dst[1] = make_float4(acc[4], acc[5], acc[6], acc[7]);
}

// ---------------- launch ------------------------------------------------------

extern "C" void kernel_launch(void* const* d_in, const int* in_sizes, int n_in,
                              void* d_out, int out_size) {
    // Resolve inputs BY ELEMENT COUNT (order-independent; all counts distinct)
    const float* x  = nullptr;
    const int*   ei = nullptr;
    const float* ew = nullptr;
    const float* W  = nullptr;
    for (int i = 0; i < n_in; i++) {
        long long sz = in_sizes[i];
        if      (sz == (long long)NN * NF) x  = (const float*)d_in[i];
        else if (sz == (long long)2 * NE)  ei = (const int*)d_in[i];
        else if (sz == (long long)NE)      ew = (const float*)d_in[i];
        else if (sz == (long long)NF * NC) W  = (const float*)d_in[i];
    }
    float* out = (float*)d_out;

    const int* row = ei;        // edge_index[0, :]
    const int* col = ei + NE;   // edge_index[1, :]

    __half* hA; cudaGetSymbolAddress((void**)&hA, d_hA);
    __half* hB; cudaGetSymbolAddress((void**)&hB, d_hB);

    // --- prep: degrees, CSR by destination (dis fused into scan) ---
    zero2_kernel<<<(NN + 255)/256, 256>>>();
    degcnt_kernel<<<(NE + 255)/256, 256>>>(row, col, ew);
    scan_dis_kernel<<<(NN + 255)/256, 256>>>();
    fill_kernel<<<(NE + 255)/256, 256>>>(row, col, ew);

    // --- project first: hA = fp16(x @ W) ---
    xw_kernel<<<(NN + 63)/64, 128>>>(x, W, hA);

    // --- three pull-mode hops (fp32 accum, fp16 intermediates) ---
    const int WARPS = (NN + 5) / 6;                  // 6 nodes per warp
    const int HOP_BLOCKS = (WARPS * 32 + 255) / 256;
    hop_h2h<<<HOP_BLOCKS, 256>>>(hA, hB);
    hop_h2h<<<HOP_BLOCKS, 256>>>(hB, hA);
    hop_h2f<<<HOP_BLOCKS, 256>>>(hA, out);
}